// round 16
// baseline (speedup 1.0000x reference)
#include <cuda_runtime.h>
#include <cuda_fp16.h>
#include <cstdint>
#include <cstddef>

#define Bx 128
#define Hx 1024
#define Fx 138
#define Tx 1024
#define NCTA 128
#define KP1 1184
#define KP2 2048
#define XPAD 160
#define NCH1 37
#define NCH2 64
#define RSW 40   // smem row stride in halves (20 words -> conflict-free)

// ---- persistent scratch ----
__device__ __half g_W1p[4096L * KP1];
__device__ __half g_W2p[4096L * KP2];
__device__ __half g_Wh1p[128L * 1024];
__device__ __half g_Wh2p[128L * 128];
__device__ float g_bs1[4096], g_bs2[4096];
__device__ __half g_xp[(size_t)Tx * Bx * XPAD];
__device__ __half g_h1[2][Bx * Hx];
__device__ __half g_hz[Bx * Hx];
__device__ __half g_h2all[(size_t)Tx * Bx * Hx];
__device__ __half g_hid[(size_t)Tx * Bx * 128];
__device__ unsigned g_cnt, g_gen;

// ---- helpers ----
__device__ __forceinline__ float sigm(float x) { return 1.f / (1.f + __expf(-x)); }
__device__ __forceinline__ void cp16h(__half* d, const __half* s) {
    uint32_t a = (uint32_t)__cvta_generic_to_shared(d);
    asm volatile("cp.async.ca.shared.global [%0], [%1], 16;" :: "r"(a), "l"(s));
}
__device__ __forceinline__ void mma16(float* c, uint32_t a0, uint32_t a1, uint32_t a2,
                                      uint32_t a3, uint32_t b0, uint32_t b1) {
    asm volatile(
        "mma.sync.aligned.m16n8k16.row.col.f32.f16.f16.f32 "
        "{%0,%1,%2,%3},{%4,%5,%6,%7},{%8,%9},{%0,%1,%2,%3};"
        : "+f"(c[0]), "+f"(c[1]), "+f"(c[2]), "+f"(c[3])
        : "r"(a0), "r"(a1), "r"(a2), "r"(a3), "r"(b0), "r"(b1));
}

__device__ __forceinline__ void gridsync() {
    __syncthreads();
    if (threadIdx.x == 0) {
        __threadfence();
        volatile unsigned* genp = &g_gen;
        unsigned gen = *genp;
        if (atomicAdd(&g_cnt, 1u) == NCTA - 1) {
            g_cnt = 0;
            __threadfence();
            *genp = gen + 1;
        } else {
            while (*genp == gen) __nanosleep(64);
        }
        __threadfence();
    }
    __syncthreads();
}

__global__ void initz() {
    for (int i = blockIdx.x * blockDim.x + threadIdx.x; i < Bx * Hx;
         i += gridDim.x * blockDim.x) {
        g_h1[0][i] = __float2half(0.f);
        g_h1[1][i] = __float2half(0.f);
        g_hz[i] = __float2half(0.f);
    }
}

__global__ void dummyk() {}

// ---- prepack: gate-interleave (32-col CTA groups) + fp16 + x pad ----
// packed row p: cta=p>>5, gate=(p>>3)&3, u=p&7 -> r = gate*1024 + (p>>5)*8 + (p&7)
__global__ void prepack(const float* __restrict__ x,
                        const float* __restrict__ Wih1, const float* __restrict__ bih1,
                        const float* __restrict__ Whh1, const float* __restrict__ bhh1,
                        const float* __restrict__ Wih2, const float* __restrict__ bih2,
                        const float* __restrict__ Whh2, const float* __restrict__ bhh2,
                        const float* __restrict__ W1, const float* __restrict__ W2) {
    long t0 = blockIdx.x * (long)blockDim.x + threadIdx.x;
    long st = (long)gridDim.x * blockDim.x;
    for (long i = t0; i < 4096L * KP2; i += st) {
        int p = (int)(i >> 11), k = (int)(i & 2047);
        int r = ((p >> 3) & 3) * 1024 + (p >> 5) * 8 + (p & 7);
        g_W2p[i] = __float2half_rn(k < 1024 ? Wih2[(long)r * 1024 + k]
                                            : Whh2[(long)r * 1024 + k - 1024]);
    }
    for (long i = t0; i < 4096L * KP1; i += st) {
        int p = (int)(i / KP1), k = (int)(i % KP1);
        int r = ((p >> 3) & 3) * 1024 + (p >> 5) * 8 + (p & 7);
        float v = 0.f;
        if (k < 1024) v = Whh1[(long)r * 1024 + k];
        else if (k < 1024 + Fx) v = Wih1[(long)r * Fx + k - 1024];
        g_W1p[i] = __float2half_rn(v);
    }
    for (long i = t0; i < (long)Tx * Bx * XPAD; i += st) {
        long rb = i / XPAD; int k = (int)(i % XPAD);
        g_xp[i] = __float2half_rn((k < Fx) ? x[rb * Fx + k] : 0.f);
    }
    for (long i = t0; i < 128L * 1024; i += st) g_Wh1p[i] = __float2half_rn(W1[i]);
    for (long i = t0; i < 128L * 128;  i += st) g_Wh2p[i] = __float2half_rn(W2[i]);
    for (long i = t0; i < 4096; i += st) {
        int p = (int)i;
        int r = ((p >> 3) & 3) * 1024 + (p >> 5) * 8 + (p & 7);
        g_bs1[p] = bih1[r] + bhh1[r];
        g_bs2[p] = bih2[r] + bhh2[r];
    }
}

// ---- persistent recurrence: 128 CTAs x 256 thr (8 warps), warp tile M16xN32 ----
__global__ void __launch_bounds__(256, 1) persist() {
    extern __shared__ __half hsm[];
    __half* As = hsm;                        // [3][128*RSW]
    __half* Bs = hsm + 3 * 128 * RSW;        // [3][32*RSW]
    float*  bb = (float*)(hsm + 3 * 128 * RSW + 3 * 32 * RSW);  // [32]
    const int tid = threadIdx.x, cta = blockIdx.x;
    const int w = tid >> 5, l = tid & 31, g = l >> 2, q = l & 3;

    float c1s[4], c2s[4];
#pragma unroll
    for (int j = 0; j < 4; j++) { c1s[j] = 0.f; c2s[j] = 0.f; }

    auto run_layer = [&](const __half* __restrict__ A0, const __half* __restrict__ A1,
                         long s1, const __half* __restrict__ W, int KP, int nch,
                         const float* __restrict__ bias, float* cs,
                         __half* __restrict__ hdst) {
        __syncthreads();   // protect bb + smem bufs vs previous layer's readers
        if (tid < 32) bb[tid] = bias[cta * 32 + tid];

        float acc[4][4];
#pragma unroll
        for (int nf = 0; nf < 4; nf++)
#pragma unroll
            for (int j = 0; j < 4; j++) acc[nf][j] = 0.f;

        auto stage = [&](int c) {
            int jb = c % 3, k0 = c << 5;
            __half* Ab = As + jb * 128 * RSW;
            __half* Bb = Bs + jb * 32 * RSW;
            const bool inA0 = (k0 < 1024);
#pragma unroll
            for (int it = 0; it < 2; it++) {
                int i = tid + it * 256;
                int r = i >> 2, q8 = i & 3;       // r: 0..127, q8: 0..3 (8 halves each)
                const __half* src = inA0 ? A0 + (size_t)r * 1024 + k0 + q8 * 8
                                         : A1 + (size_t)r * s1 + (k0 - 1024) + q8 * 8;
                cp16h(Ab + r * RSW + q8 * 8, src);
            }
            if (tid < 128) {
                int n = tid >> 2, q8 = tid & 3;   // 32 rows x 4
                cp16h(Bb + n * RSW + q8 * 8,
                      W + (size_t)(cta * 32 + n) * KP + k0 + q8 * 8);
            }
            asm volatile("cp.async.commit_group;" ::: "memory");
        };

        stage(0); stage(1);
        for (int c = 0; c < nch; c++) {
            if (c + 1 < nch) asm volatile("cp.async.wait_group 1;" ::: "memory");
            else             asm volatile("cp.async.wait_group 0;" ::: "memory");
            __syncthreads();
            if (c + 2 < nch) stage(c + 2);
            const uint32_t* Aw = (const uint32_t*)(As + (c % 3) * 128 * RSW);  // 20 words/row
            const uint32_t* Bw = (const uint32_t*)(Bs + (c % 3) * 32 * RSW);
#pragma unroll
            for (int kb = 0; kb < 2; kb++) {       // two k16 blocks per K32 chunk
                int ko = kb * 8;                   // word offset
                int r0 = 16 * w + g;
                uint32_t a0 = Aw[r0 * 20 + ko + q];
                uint32_t a1 = Aw[(r0 + 8) * 20 + ko + q];
                uint32_t a2 = Aw[r0 * 20 + ko + q + 4];
                uint32_t a3 = Aw[(r0 + 8) * 20 + ko + q + 4];
#pragma unroll
                for (int nf = 0; nf < 4; nf++) {
                    uint32_t b0 = Bw[(8 * nf + g) * 20 + ko + q];
                    uint32_t b1 = Bw[(8 * nf + g) * 20 + ko + q + 4];
                    mma16(acc[nf], a0, a1, a2, a3, b0, b1);
                }
            }
        }
        // epilogue: gates -> cell update -> h (half2 store)
#pragma unroll
        for (int jh = 0; jh < 2; jh++) {           // jh: row-half (j>>1)
            int m = 16 * w + g + 8 * jh;
            __half hv[2];
#pragma unroll
            for (int jl = 0; jl < 2; jl++) {
                int j = 2 * jh + jl;
                int u = 2 * q + jl;
                float iv = sigm(acc[0][j] + bb[u]);
                float fv = sigm(acc[1][j] + bb[8 + u]);
                float gv = tanhf(acc[2][j] + bb[16 + u]);
                float ov = sigm(acc[3][j] + bb[24 + u]);
                float cn = fv * cs[j] + iv * gv;
                cs[j] = cn;
                hv[jl] = __float2half_rn(ov * tanhf(cn));
            }
            *(__half2*)(hdst + (size_t)m * Hx + cta * 8 + 2 * q) =
                __halves2half2(hv[0], hv[1]);
        }
    };

    // t=0 layer1, then per-step: sync; L2(t); L1(t+1)
    run_layer(g_h1[1], g_xp, XPAD, g_W1p, KP1, NCH1, g_bs1, c1s, g_h1[0]);
    for (int t = 0; t < Tx; t++) {
        gridsync();
        const __half* h1w = g_h1[t & 1];
        const __half* h2r = (t == 0) ? g_hz : g_h2all + (size_t)(t - 1) * Bx * Hx;
        __half*       h2w = g_h2all + (size_t)t * Bx * Hx;
        run_layer(h1w, h2r, 1024, g_W2p, KP2, NCH2, g_bs2, c2s, h2w);
        if (t + 1 < Tx)
            run_layer(h1w, g_xp + (size_t)(t + 1) * Bx * XPAD, XPAD,
                      g_W1p, KP1, NCH1, g_bs1, c1s, g_h1[(t + 1) & 1]);
    }
}

// ---- MLP head: fp16 m16n8k16, 256 thr, warp tile M16xN32 ----
struct SMh {
    __half As[2][128 * RSW];
    __half Bs[2][32 * RSW];
    float bb[32];
};

// MODE 1: selu -> half out (stride 128); MODE 2: plain -> float out (stride 128)
template <int MODE, typename OUT>
__device__ __forceinline__ void hgemm(const __half* __restrict__ A0, long s0,
                                      const __half* __restrict__ W, int KP,
                                      const float* __restrict__ bias,
                                      OUT* out, int cta, int row0, SMh& sm) {
    const int tid = threadIdx.x;
    const int w = tid >> 5, l = tid & 31, g = l >> 2, q = l & 3;
    const int nch = KP >> 5;
    if (tid < 32) sm.bb[tid] = bias[cta * 32 + tid];
    float acc[4][4];
#pragma unroll
    for (int a = 0; a < 4; a++)
#pragma unroll
        for (int j = 0; j < 4; j++) acc[a][j] = 0.f;

    auto stg = [&](int ch) {
        int k0 = ch << 5;
        __half* Ab = sm.As[ch & 1];
        __half* Bb = sm.Bs[ch & 1];
#pragma unroll
        for (int it = 0; it < 2; it++) {
            int i = tid + it * 256;
            int r = i >> 2, q8 = i & 3;
            cp16h(Ab + r * RSW + q8 * 8, A0 + (size_t)(row0 + r) * s0 + k0 + q8 * 8);
        }
        if (tid < 128) {
            int n = tid >> 2, q8 = tid & 3;
            cp16h(Bb + n * RSW + q8 * 8, W + (size_t)(cta * 32 + n) * KP + k0 + q8 * 8);
        }
        asm volatile("cp.async.commit_group;");
    };

    stg(0);
    for (int ch = 0; ch < nch; ch++) {
        if (ch + 1 < nch) { stg(ch + 1); asm volatile("cp.async.wait_group 1;"); }
        else              { asm volatile("cp.async.wait_group 0;"); }
        __syncthreads();
        const uint32_t* Aw = (const uint32_t*)sm.As[ch & 1];
        const uint32_t* Bw = (const uint32_t*)sm.Bs[ch & 1];
#pragma unroll
        for (int kb = 0; kb < 2; kb++) {
            int ko = kb * 8;
            uint32_t a0 = Aw[(16 * w + g) * 20 + ko + q];
            uint32_t a1 = Aw[(16 * w + g + 8) * 20 + ko + q];
            uint32_t a2 = Aw[(16 * w + g) * 20 + ko + q + 4];
            uint32_t a3 = Aw[(16 * w + g + 8) * 20 + ko + q + 4];
#pragma unroll
            for (int nf = 0; nf < 4; nf++) {
                uint32_t b0 = Bw[(8 * nf + g) * 20 + ko + q];
                uint32_t b1 = Bw[(8 * nf + g) * 20 + ko + q + 4];
                mma16(acc[nf], a0, a1, a2, a3, b0, b1);
            }
        }
        __syncthreads();
    }
#pragma unroll
    for (int nf = 0; nf < 4; nf++)
#pragma unroll
        for (int j = 0; j < 4; j++) {
            int m = 16 * w + g + 8 * (j >> 1);
            int col = cta * 32 + 8 * nf + 2 * q + (j & 1);
            float v = acc[nf][j] + sm.bb[8 * nf + 2 * q + (j & 1)];
            if (MODE == 1) {
                v = v > 0.f ? 1.0507009873554805f * v
                            : 1.7580993408473766f * (__expf(v) - 1.f);
                ((__half*)out)[(size_t)(row0 + m) * 128 + col] = __float2half_rn(v);
            } else {
                ((float*)out)[(size_t)(row0 + m) * 128 + col] = v;
            }
        }
}

__global__ void __launch_bounds__(256) headk1(const __half* __restrict__ A, long sA,
                                              const __half* __restrict__ W, int KP,
                                              const float* __restrict__ bias, __half* out) {
    __shared__ SMh sm;
    hgemm<1, __half>(A, sA, W, KP, bias, out, blockIdx.x, blockIdx.y * 128, sm);
}
__global__ void __launch_bounds__(256) headk2(const __half* __restrict__ A, long sA,
                                              const __half* __restrict__ W, int KP,
                                              const float* __restrict__ bias, float* out) {
    __shared__ SMh sm;
    hgemm<2, float>(A, sA, W, KP, bias, out, blockIdx.x, blockIdx.y * 128, sm);
}

extern "C" void kernel_launch(void* const* d_in, const int* in_sizes, int n_in,
                              void* d_out, int out_size) {
    const float* x    = (const float*)d_in[0];
    const float* Wih1 = (const float*)d_in[1]; const float* bih1 = (const float*)d_in[2];
    const float* Whh1 = (const float*)d_in[3]; const float* bhh1 = (const float*)d_in[4];
    const float* Wih2 = (const float*)d_in[5]; const float* bih2 = (const float*)d_in[6];
    const float* Whh2 = (const float*)d_in[7]; const float* bhh2 = (const float*)d_in[8];
    const float* W1   = (const float*)d_in[9]; const float* b1   = (const float*)d_in[10];
    const float* W2   = (const float*)d_in[11]; const float* b2  = (const float*)d_in[12];

    __half *Wh1p, *Wh2p, *h2all, *hid;
    cudaGetSymbolAddress((void**)&Wh1p,  g_Wh1p);
    cudaGetSymbolAddress((void**)&Wh2p,  g_Wh2p);
    cudaGetSymbolAddress((void**)&h2all, g_h2all);
    cudaGetSymbolAddress((void**)&hid,   g_hid);

    int psm = (3 * 128 * RSW + 3 * 32 * RSW) * 2 + 32 * 4;
    cudaFuncSetAttribute(persist, cudaFuncAttributeMaxDynamicSharedMemorySize, psm);

    initz<<<128, 256>>>();
    prepack<<<1024, 256>>>(x, Wih1, bih1, Whh1, bhh1, Wih2, bih2, Whh2, bhh2, W1, W2);
    dummyk<<<1, 32>>>();
    persist<<<NCTA, 256, psm>>>();   // 4th launch -> ncu capture target
    headk1<<<dim3(4, 1024), 256>>>(h2all, 1024, Wh1p, 1024, b1, hid);
    headk2<<<dim3(4, 1024), 256>>>(hid, 128, Wh2p, 128, b2, (float*)d_out);
}